// round 4
// baseline (speedup 1.0000x reference)
#include <cuda_runtime.h>
#include <cuda_bf16.h>

// Scratch (no cudaMalloc allowed): per-class accumulators + means.
__device__ double             g_sum[3];
__device__ unsigned long long g_cnt[3];
__device__ float              g_mean[3];

__global__ void zero_kernel() {
    if (threadIdx.x < 3) {
        g_sum[threadIdx.x] = 0.0;
        g_cnt[threadIdx.x] = 0ULL;
    }
}

// Reduce: per-class global sum of feats and pixel counts.
// 4 pixels per thread iteration: int4 inst + 3x float4 feats (12 floats).
__global__ void __launch_bounds__(256) reduce_kernel(
        const float4* __restrict__ feats4,
        const int4*  __restrict__ inst4,
        const float* __restrict__ feats,
        const int*   __restrict__ inst,
        int ngroups, int rem) {
    float s0 = 0.f, s1 = 0.f, s2 = 0.f;
    int   c0 = 0,   c1 = 0,   c2 = 0;

    const int tid    = blockIdx.x * blockDim.x + threadIdx.x;
    const int stride = gridDim.x * blockDim.x;

    for (int g = tid; g < ngroups; g += stride) {
        int4   ii = __ldg(&inst4[(size_t)g]);              // keep cached: reused by scatter via L2
        float4 a  = __ldcs(&feats4[(size_t)3 * g + 0]);    // evict-first: feats never reused
        float4 b  = __ldcs(&feats4[(size_t)3 * g + 1]);
        float4 c  = __ldcs(&feats4[(size_t)3 * g + 2]);
        // pixel sums across the 3 channels
        float p0 = a.x + a.y + a.z;
        float p1 = a.w + b.x + b.y;
        float p2 = b.z + b.w + c.x;
        float p3 = c.y + c.z + c.w;

        // predicated accumulation (classes are 0/1/2)
        s0 += (ii.x == 0) ? p0 : 0.f;  c0 += (ii.x == 0);
        s1 += (ii.x == 1) ? p0 : 0.f;  c1 += (ii.x == 1);
        s2 += (ii.x == 2) ? p0 : 0.f;  c2 += (ii.x == 2);

        s0 += (ii.y == 0) ? p1 : 0.f;  c0 += (ii.y == 0);
        s1 += (ii.y == 1) ? p1 : 0.f;  c1 += (ii.y == 1);
        s2 += (ii.y == 2) ? p1 : 0.f;  c2 += (ii.y == 2);

        s0 += (ii.z == 0) ? p2 : 0.f;  c0 += (ii.z == 0);
        s1 += (ii.z == 1) ? p2 : 0.f;  c1 += (ii.z == 1);
        s2 += (ii.z == 2) ? p2 : 0.f;  c2 += (ii.z == 2);

        s0 += (ii.w == 0) ? p3 : 0.f;  c0 += (ii.w == 0);
        s1 += (ii.w == 1) ? p3 : 0.f;  c1 += (ii.w == 1);
        s2 += (ii.w == 2) ? p3 : 0.f;  c2 += (ii.w == 2);
    }

    // scalar tail (npix % 4), handled by the first `rem` threads
    if (tid < rem) {
        size_t p = (size_t)ngroups * 4 + tid;
        int cls = inst[p];
        float v = feats[3 * p + 0] + feats[3 * p + 1] + feats[3 * p + 2];
        s0 += (cls == 0) ? v : 0.f;  c0 += (cls == 0);
        s1 += (cls == 1) ? v : 0.f;  c1 += (cls == 1);
        s2 += (cls == 2) ? v : 0.f;  c2 += (cls == 2);
    }

    // warp reduce
    #pragma unroll
    for (int off = 16; off > 0; off >>= 1) {
        s0 += __shfl_down_sync(0xFFFFFFFFu, s0, off);
        s1 += __shfl_down_sync(0xFFFFFFFFu, s1, off);
        s2 += __shfl_down_sync(0xFFFFFFFFu, s2, off);
        c0 += __shfl_down_sync(0xFFFFFFFFu, c0, off);
        c1 += __shfl_down_sync(0xFFFFFFFFu, c1, off);
        c2 += __shfl_down_sync(0xFFFFFFFFu, c2, off);
    }

    __shared__ float sh_s[3][8];
    __shared__ int   sh_c[3][8];
    int lane = threadIdx.x & 31;
    int wid  = threadIdx.x >> 5;
    if (lane == 0) {
        sh_s[0][wid] = s0; sh_s[1][wid] = s1; sh_s[2][wid] = s2;
        sh_c[0][wid] = c0; sh_c[1][wid] = c1; sh_c[2][wid] = c2;
    }
    __syncthreads();

    if (threadIdx.x < 3) {
        int cls = threadIdx.x;
        float     fs = 0.f;
        long long ic = 0;
        int nwarps = blockDim.x >> 5;
        for (int w = 0; w < nwarps; w++) { fs += sh_s[cls][w]; ic += sh_c[cls][w]; }
        atomicAdd(&g_sum[cls], (double)fs);
        atomicAdd(&g_cnt[cls], (unsigned long long)ic);
    }
}

__global__ void finalize_kernel() {
    if (threadIdx.x < 3) {
        int c = threadIdx.x;
        // cnt in the reference includes the 3 channels
        double denom = 3.0 * (double)g_cnt[c];
        g_mean[c] = (float)(g_sum[c] / denom);
    }
}

// Scatter: out[pixel, ch] = mean[inst[pixel]] — never reads feats.
__global__ void __launch_bounds__(256) scatter_kernel(
        const int4* __restrict__ inst4,
        float4* __restrict__ out4,
        const int* __restrict__ inst,
        float* __restrict__ out,
        int ngroups, int rem) {
    const float m0 = g_mean[0];
    const float m1 = g_mean[1];
    const float m2 = g_mean[2];

    const int tid    = blockIdx.x * blockDim.x + threadIdx.x;
    const int stride = gridDim.x * blockDim.x;

    for (int g = tid; g < ngroups; g += stride) {
        int4 ii = __ldg(&inst4[(size_t)g]);    // ideally L2-resident from reduce
        float mA = (ii.x == 0) ? m0 : ((ii.x == 1) ? m1 : m2);
        float mB = (ii.y == 0) ? m0 : ((ii.y == 1) ? m1 : m2);
        float mC = (ii.z == 0) ? m0 : ((ii.z == 1) ? m1 : m2);
        float mD = (ii.w == 0) ? m0 : ((ii.w == 1) ? m1 : m2);
        __stcs(&out4[(size_t)3 * g + 0], make_float4(mA, mA, mA, mB));
        __stcs(&out4[(size_t)3 * g + 1], make_float4(mB, mB, mC, mC));
        __stcs(&out4[(size_t)3 * g + 2], make_float4(mC, mD, mD, mD));
    }

    if (tid < rem) {
        size_t p = (size_t)ngroups * 4 + tid;
        int cls = inst[p];
        float m = (cls == 0) ? m0 : ((cls == 1) ? m1 : m2);
        out[3 * p + 0] = m;
        out[3 * p + 1] = m;
        out[3 * p + 2] = m;
    }
}

extern "C" void kernel_launch(void* const* d_in, const int* in_sizes, int n_in,
                              void* d_out, int out_size) {
    const float* feats = (const float*)d_in[0];
    const int*   inst  = (const int*)d_in[1];
    float*       out   = (float*)d_out;

    const int npix    = in_sizes[1];      // one inst entry per pixel
    const int ngroups = npix >> 2;        // groups of 4 pixels
    const int rem     = npix & 3;

    const int threads = 256;
    const int blocks  = 1216;             // 152 SMs * 8 CTAs; grid-stride covers the rest

    zero_kernel<<<1, 32>>>();
    reduce_kernel<<<blocks, threads>>>((const float4*)feats, (const int4*)inst,
                                       feats, inst, ngroups, rem);
    finalize_kernel<<<1, 32>>>();
    scatter_kernel<<<blocks, threads>>>((const int4*)inst, (float4*)out,
                                        inst, out, ngroups, rem);
}